// round 14
// baseline (speedup 1.0000x reference)
#include <cuda_runtime.h>
#include <math.h>

#define Bz   128
#define Hh   512
#define G4   2048
#define Tt   256
#define INZ  64
#define OUTL 512
#define NBLK 128

typedef unsigned long long u64;

// ---------------- device scratch ----------------
__device__ float g_xpe[(size_t)Tt * Bz * G4];   // [t][b][4H]
__device__ float g_xpd[(size_t)Tt * Bz * G4];
__device__ float g_hse[(size_t)Tt * Hh * Bz];   // [t][h][b] (ring + output)
__device__ float g_hsd[(size_t)Tt * Hh * Bz];
__device__ float g_hA[Hh * Bz];                 // initial h (encoder)
__device__ float g_h2A[Hh * Bz];                // initial h (decoder)
__device__ float g_fcp[(size_t)Tt * Bz * OUTL];
__device__ unsigned g_ck[8];                    // [layer][chunk] producer counters

// ---------------- f32x2 helpers ----------------
__device__ __forceinline__ u64 pack2(float lo, float hi) {
    u64 r; asm("mov.b64 %0,{%1,%2};" : "=l"(r) : "f"(lo), "f"(hi)); return r;
}
__device__ __forceinline__ void unpack2(u64 v, float& lo, float& hi) {
    asm("mov.b64 {%0,%1},%2;" : "=f"(lo), "=f"(hi) : "l"(v));
}
__device__ __forceinline__ u64 fma2(u64 a, u64 b, u64 c) {
    u64 d; asm("fma.rn.f32x2 %0,%1,%2,%3;" : "=l"(d) : "l"(a), "l"(b), "l"(c)); return d;
}
__device__ __forceinline__ u64 add2(u64 a, u64 b) {
    u64 d; asm("add.rn.f32x2 %0,%1,%2;" : "=l"(d) : "l"(a), "l"(b)); return d;
}
__device__ __forceinline__ float fsig(float x) { return __fdividef(1.f, 1.f + __expf(-x)); }
__device__ __forceinline__ float ftanh_(float x) { return 2.f * fsig(2.f * x) - 1.f; }
__device__ __forceinline__ unsigned ld_acq(const unsigned* p) {
    unsigned v; asm volatile("ld.acquire.gpu.u32 %0,[%1];" : "=r"(v) : "l"(p) : "memory"); return v;
}
__device__ __forceinline__ void red_rel_add(unsigned* p, unsigned v) {
    asm volatile("red.release.gpu.global.add.u32 [%0],%1;" :: "l"(p), "r"(v) : "memory");
}

// ---------------- init ----------------
__global__ void init_h(const float* __restrict__ h0e, const float* __restrict__ h0d) {
    int i = blockIdx.x * blockDim.x + threadIdx.x;
    if (i < Hh * Bz) {
        int k = i >> 7, b = i & 127;
        g_hA[i]  = h0e[b * Hh + k];
        g_h2A[i] = h0d[b * Hh + k];
    }
}
__global__ void init_bar() {
    if (threadIdx.x < 8) g_ck[threadIdx.x] = 0u;
}

// ---------------- input projection GEMM (f32x2, double-buffered smem) ----------------
template <int MODE>
__global__ void __launch_bounds__(256)
inproj_gemm(const float* __restrict__ A_or_x, const float* __restrict__ W,
            const float* __restrict__ b0v, const float* __restrict__ b1v,
            float* __restrict__ out, int K) {
    __shared__ __align__(16) float As[2][8][128];
    __shared__ __align__(16) float Bs[2][8][128];

    const int m0  = blockIdx.y * 128;
    const int n0  = blockIdx.x * 128;
    const int tid = threadIdx.x;
    const int txx = tid & 15;
    const int tyy = tid >> 4;
    const int lrow = tid >> 1;
    const int lkq  = (tid & 1) * 4;
    const int arow = tid >> 5;
    const int acol = (tid & 31) * 4;

    u64 acc[8][4];
#pragma unroll
    for (int i = 0; i < 8; i++)
#pragma unroll
        for (int j = 0; j < 4; j++) acc[i][j] = 0ull;

    float4 aPf, bPf;
    float  aPfS[4];

    auto loadA = [&](int k0) {
        if (MODE == 1) {
            aPf = *reinterpret_cast<const float4*>(
                &A_or_x[(size_t)blockIdx.y * Hh * Bz + (size_t)(k0 + arow) * Bz + acol]);
        } else {
            int m = m0 + lrow;
            int tt = m >> 7, b = m & 127;
#pragma unroll
            for (int i = 0; i < 4; i++)
                aPfS[i] = A_or_x[(size_t)b * (INZ * Tt) + (size_t)(k0 + lkq + i) * Tt + tt];
        }
        bPf = *reinterpret_cast<const float4*>(&W[(size_t)(n0 + lrow) * K + k0 + lkq]);
    };
    auto storeS = [&](int st) {
        if (MODE == 1) {
            *reinterpret_cast<float4*>(&As[st][arow][acol]) = aPf;
        } else {
#pragma unroll
            for (int i = 0; i < 4; i++) As[st][lkq + i][lrow] = aPfS[i];
        }
        Bs[st][lkq + 0][lrow] = bPf.x; Bs[st][lkq + 1][lrow] = bPf.y;
        Bs[st][lkq + 2][lrow] = bPf.z; Bs[st][lkq + 3][lrow] = bPf.w;
    };

    const int NIT = K >> 3;
    loadA(0);
    storeS(0);
    __syncthreads();

    for (int it = 0; it < NIT; it++) {
        const int s = it & 1;
        if (it + 1 < NIT) loadA((it + 1) << 3);

#pragma unroll
        for (int kk = 0; kk < 8; kk++) {
            float a[8];
            *reinterpret_cast<float4*>(&a[0]) = *reinterpret_cast<const float4*>(&As[s][kk][tyy * 8]);
            *reinterpret_cast<float4*>(&a[4]) = *reinterpret_cast<const float4*>(&As[s][kk][tyy * 8 + 4]);
            ulonglong2 bp01 = *reinterpret_cast<const ulonglong2*>(&Bs[s][kk][txx * 8]);
            ulonglong2 bp23 = *reinterpret_cast<const ulonglong2*>(&Bs[s][kk][txx * 8 + 4]);
            u64 bp[4] = {bp01.x, bp01.y, bp23.x, bp23.y};
#pragma unroll
            for (int i = 0; i < 8; i++) {
                u64 as = pack2(a[i], a[i]);
#pragma unroll
                for (int j = 0; j < 4; j++)
                    acc[i][j] = fma2(as, bp[j], acc[i][j]);
            }
        }

        if (it + 1 < NIT) storeS(s ^ 1);
        __syncthreads();
    }

#pragma unroll
    for (int i = 0; i < 8; i++) {
        int m = m0 + tyy * 8 + i;
#pragma unroll
        for (int j = 0; j < 4; j++) {
            int n = n0 + txx * 8 + 2 * j;
            float lo, hi; unpack2(acc[i][j], lo, hi);
            float2 v = make_float2(lo + b0v[n] + b1v[n], hi + b0v[n + 1] + b1v[n + 1]);
            *reinterpret_cast<float2*>(&out[(size_t)m * G4 + n]) = v;
        }
    }
}

// ---------------- persistent LSTM (R12, unchanged) ----------------
__global__ void __launch_bounds__(512, 1)
lstm_persistent(const float* __restrict__ xp_all,   // [t][b][2048]
                const float* __restrict__ whh,      // [2048][512]
                const float* __restrict__ c0,       // [b][512]
                const float* __restrict__ h0buf,    // [512][128] initial h
                float* __restrict__ hs_t,           // [t][512][128] ring + output
                int layer) {
    extern __shared__ char sm_[];
    float* ws    = (float*)sm_;                    // [512][16]  32KB
    float* hb    = (float*)(sm_ + 32768);          // [2][128][128] 128KB (reused as red)
    u64*   red64 = (u64*)(sm_ + 32768);            // [8][64][17] u64 overlay
    float* xs    = (float*)(sm_ + 32768 + 135168); // [128][20] 10KB

    const int tid  = threadIdx.x;
    const int lane = tid & 31;
    const int wrp  = tid >> 5;
    const int ks   = wrp & 7;
    const int bh   = wrp >> 3;
    const int rh   = lane >> 4;
    const int bo   = lane & 15;
    const int hidx0 = blockIdx.x * 4;
    const int myGrp = blockIdx.x >> 5;

    const int eb  = tid & 127;
    const int ehh = tid >> 7;
    const int erh = ehh >> 1, ehp = ehh & 1;
    const int e_bh = eb >> 6;
    const int e_bo = (eb >> 2) & 15;
    const int e_j  = eb & 3;
    const int rd_off = (e_bh * 32 + erh * 16 + e_bo) * 17 + e_j * 4 + ehp * 2;

    unsigned* ck = &g_ck[layer * 4];

    for (int r = tid; r < 8192; r += 512) {
        int k = r & 511, idx = r >> 9;
        int hh = idx >> 2, q = idx & 3;
        ws[k * 16 + idx] = whh[(size_t)(q * Hh + hidx0 + hh) * Hh + k];
    }
    float creg = c0[(size_t)eb * Hh + hidx0 + ehh];

    const unsigned hb_s = (unsigned)__cvta_generic_to_shared(hb);

    float4 xr = *reinterpret_cast<const float4*>(
        &xp_all[(size_t)(tid >> 2) * G4 + (tid & 3) * Hh + hidx0]);

    __syncthreads();

    for (int t = 0; t < Tt; t++) {
        const float* hp = (t == 0) ? h0buf : (hs_t + (size_t)(t - 1) * Hh * Bz);

        if (tid == 0 && t > 0) {
            unsigned target = (unsigned)(32 * t);
            while (ld_acq(&ck[0]) < target) {}
        }
        __syncthreads();
        {
            unsigned sa = hb_s + tid * 16;
            const char* gp = (const char*)hp + tid * 16;
#pragma unroll
            for (int i = 0; i < 8; i++)
                asm volatile("cp.async.cg.shared.global [%0], [%1], 16;"
                             :: "r"(sa + i * 8192), "l"(gp + i * 8192));
            asm volatile("cp.async.commit_group;" ::: "memory");
        }

        u64 acc[4][4];
#pragma unroll
        for (int j = 0; j < 4; j++)
#pragma unroll
            for (int p = 0; p < 4; p++) acc[j][p] = 0ull;

#pragma unroll
        for (int c = 0; c < 4; c++) {
            asm volatile("cp.async.wait_group 0;" ::: "memory");
            if (tid == 0 && c < 3 && t > 0) {
                unsigned target = (unsigned)(32 * t);
                while (ld_acq(&ck[c + 1]) < target) {}
            }
            __syncthreads();

            if (c < 3) {
                unsigned sa = hb_s + ((c + 1) & 1) * 65536 + tid * 16;
                const char* gp = (const char*)(hp + (c + 1) * 16384) + tid * 16;
#pragma unroll
                for (int i = 0; i < 8; i++)
                    asm volatile("cp.async.cg.shared.global [%0], [%1], 16;"
                                 :: "r"(sa + i * 8192), "l"(gp + i * 8192));
                asm volatile("cp.async.commit_group;" ::: "memory");
            }

            const float* bufk = hb + (c & 1) * 16384 + (size_t)(ks * 16) * 128 + bh * 64 + bo * 4;
            const float* wsk  = ws + (size_t)(c * 128 + ks * 16) * 16 + rh * 8;
#pragma unroll
            for (int kk = 0; kk < 16; kk++) {
                float4 hv = *reinterpret_cast<const float4*>(bufk + (size_t)kk * 128);
                ulonglong2 wa = *reinterpret_cast<const ulonglong2*>(wsk + (size_t)kk * 16);
                ulonglong2 wb = *reinterpret_cast<const ulonglong2*>(wsk + (size_t)kk * 16 + 4);
                float hvv[4] = {hv.x, hv.y, hv.z, hv.w};
#pragma unroll
                for (int j = 0; j < 4; j++) {
                    u64 hs = pack2(hvv[j], hvv[j]);
                    acc[j][0] = fma2(hs, wa.x, acc[j][0]);
                    acc[j][1] = fma2(hs, wa.y, acc[j][1]);
                    acc[j][2] = fma2(hs, wb.x, acc[j][2]);
                    acc[j][3] = fma2(hs, wb.y, acc[j][3]);
                }
            }
        }

        __syncthreads();

        *reinterpret_cast<float4*>(&xs[(tid >> 2) * 20 + (tid & 3) * 4]) = xr;

        {
            u64* rp = red64 + (size_t)ks * 1088 + (size_t)(bh * 32 + lane) * 17;
#pragma unroll
            for (int j = 0; j < 4; j++)
#pragma unroll
                for (int p = 0; p < 4; p++) rp[j * 4 + p] = acc[j][p];
        }
        __syncthreads();

        u64 s0 = 0ull, s1 = 0ull;
        {
            const u64* rp = red64 + rd_off;
#pragma unroll
            for (int g = 0; g < 8; g++) {
                s0 = add2(s0, rp[(size_t)g * 1088]);
                s1 = add2(s1, rp[(size_t)g * 1088 + 1]);
            }
        }

        {
            float gi_, gf_, gg_, go_;
            unpack2(s0, gi_, gf_);
            unpack2(s1, gg_, go_);
            const float* xb = xs + eb * 20 + ehh;
            float gi = gi_ + xb[0];
            float gf = gf_ + xb[4];
            float gg = gg_ + xb[8];
            float go = go_ + xb[12];
            float cc = fsig(gf) * creg + fsig(gi) * ftanh_(gg);
            creg = cc;
            float h = fsig(go) * ftanh_(cc);
            hs_t[(size_t)t * Hh * Bz + (hidx0 + ehh) * Bz + eb] = h;
        }

        if (t + 1 < Tt)
            xr = *reinterpret_cast<const float4*>(
                &xp_all[(size_t)(t + 1) * Bz * G4 +
                        (size_t)(tid >> 2) * G4 + (tid & 3) * Hh + hidx0]);

        __syncthreads();
        if (tid == 0) red_rel_add(&ck[myGrp], 1u);
    }
}

// ---------------- encoder output transpose ----------------
__global__ void __launch_bounds__(256)
enc_transpose(const float* __restrict__ hs_t, float* __restrict__ out) {
    __shared__ float tile[32][33];
    int t0 = blockIdx.x * 32, b0 = blockIdx.y * 32, h = blockIdx.z;
    int tx = threadIdx.x & 31, ty = threadIdx.x >> 5;
#pragma unroll
    for (int i = ty; i < 32; i += 8)
        tile[i][tx] = hs_t[(size_t)(t0 + i) * (Hh * Bz) + (size_t)h * Bz + b0 + tx];
    __syncthreads();
#pragma unroll
    for (int i = ty; i < 32; i += 8)
        out[(size_t)(b0 + i) * (Hh * Tt) + (size_t)h * Tt + t0 + tx] = tile[tx][i];
}

// ---------------- FC partial GEMM (f32x2, k-split over t; R12 version) ----------------
__global__ void __launch_bounds__(256)
fc_partial(const float* __restrict__ hsd_t, const float* __restrict__ Wfc) {
    const int t  = blockIdx.y;
    const int o0 = blockIdx.x * 128;
    const int tid = threadIdx.x;
    const int txx = tid & 15;
    const int tyy = tid >> 4;
    const int lrow = tid >> 1;
    const int lkq  = (tid & 1) * 4;
    const int arow = tid >> 5;
    const int acol = (tid & 31) * 4;

    __shared__ __align__(16) float As[8][128];
    __shared__ __align__(16) float Bs[8][128];

    u64 acc[8][4];
#pragma unroll
    for (int i = 0; i < 8; i++)
#pragma unroll
        for (int j = 0; j < 4; j++) acc[i][j] = 0ull;

    const float* Abase = hsd_t + (size_t)t * (Hh * Bz);

    for (int h0 = 0; h0 < Hh; h0 += 8) {
        *reinterpret_cast<float4*>(&As[arow][acol]) =
            *reinterpret_cast<const float4*>(&Abase[(size_t)(h0 + arow) * Bz + acol]);
#pragma unroll
        for (int i = 0; i < 4; i++)
            Bs[lkq + i][lrow] = Wfc[(size_t)(o0 + lrow) * (Hh * Tt) + (size_t)(h0 + lkq + i) * Tt + t];
        __syncthreads();
#pragma unroll
        for (int kk = 0; kk < 8; kk++) {
            float a[8];
            *reinterpret_cast<float4*>(&a[0]) = *reinterpret_cast<const float4*>(&As[kk][tyy * 8]);
            *reinterpret_cast<float4*>(&a[4]) = *reinterpret_cast<const float4*>(&As[kk][tyy * 8 + 4]);
            ulonglong2 bp01 = *reinterpret_cast<const ulonglong2*>(&Bs[kk][txx * 8]);
            ulonglong2 bp23 = *reinterpret_cast<const ulonglong2*>(&Bs[kk][txx * 8 + 4]);
            u64 bp[4] = {bp01.x, bp01.y, bp23.x, bp23.y};
#pragma unroll
            for (int i = 0; i < 8; i++) {
                u64 as = pack2(a[i], a[i]);
#pragma unroll
                for (int j = 0; j < 4; j++)
                    acc[i][j] = fma2(as, bp[j], acc[i][j]);
            }
        }
        __syncthreads();
    }

    float* part = g_fcp + (size_t)t * (Bz * OUTL);
#pragma unroll
    for (int i = 0; i < 8; i++) {
        int b = tyy * 8 + i;
#pragma unroll
        for (int j = 0; j < 4; j++) {
            float lo, hi; unpack2(acc[i][j], lo, hi);
            *reinterpret_cast<float2*>(&part[(size_t)b * OUTL + o0 + txx * 8 + 2 * j]) =
                make_float2(lo, hi);
        }
    }
}

__global__ void fc_reduce(const float* __restrict__ bfc, float* __restrict__ decoded) {
    int i = blockIdx.x * blockDim.x + threadIdx.x;
    if (i >= Bz * OUTL) return;
    float s = bfc[i & (OUTL - 1)];
    for (int t = 0; t < Tt; t++) s += g_fcp[(size_t)t * (Bz * OUTL) + i];
    decoded[i] = s;
}

// ---------------- launch ----------------
extern "C" void kernel_launch(void* const* d_in, const int* in_sizes, int n_in,
                              void* d_out, int out_size) {
    const float* x     = (const float*)d_in[0];
    const float* h0e   = (const float*)d_in[1];
    const float* c0e   = (const float*)d_in[2];
    const float* Wih_e = (const float*)d_in[3];
    const float* Whh_e = (const float*)d_in[4];
    const float* bih_e = (const float*)d_in[5];
    const float* bhh_e = (const float*)d_in[6];
    const float* h0d   = (const float*)d_in[7];
    const float* c0d   = (const float*)d_in[8];
    const float* Wih_d = (const float*)d_in[9];
    const float* Whh_d = (const float*)d_in[10];
    const float* bih_d = (const float*)d_in[11];
    const float* bhh_d = (const float*)d_in[12];
    const float* Wfc   = (const float*)d_in[13];
    const float* bfc   = (const float*)d_in[14];

    float* out = (float*)d_out;
    float* enc_out = out;
    float* decoded = out + (size_t)Bz * Hh * Tt;

    float *xpe, *xpd, *hse, *hsd, *hA, *h2A;
    cudaGetSymbolAddress((void**)&xpe, g_xpe);
    cudaGetSymbolAddress((void**)&xpd, g_xpd);
    cudaGetSymbolAddress((void**)&hse, g_hse);
    cudaGetSymbolAddress((void**)&hsd, g_hsd);
    cudaGetSymbolAddress((void**)&hA,  g_hA);
    cudaGetSymbolAddress((void**)&h2A, g_h2A);

    const int SMEM = 32768 + 135168 + 10240;   // 178176
    cudaFuncSetAttribute(lstm_persistent, cudaFuncAttributeMaxDynamicSharedMemorySize, SMEM);

    init_h<<<(Hh * Bz + 255) / 256, 256>>>(h0e, h0d);
    init_bar<<<1, 32>>>();

    inproj_gemm<0><<<dim3(16, 256), 256>>>(x, Wih_e, bih_e, bhh_e, xpe, INZ);

    lstm_persistent<<<NBLK, 512, SMEM>>>(xpe, Whh_e, c0e, hA, hse, 0);

    inproj_gemm<1><<<dim3(16, 256), 256>>>(hse, Wih_d, bih_d, bhh_d, xpd, Hh);

    lstm_persistent<<<NBLK, 512, SMEM>>>(xpd, Whh_d, c0d, h2A, hsd, 1);

    enc_transpose<<<dim3(Tt / 32, Bz / 32, Hh), 256>>>(hse, enc_out);

    fc_partial<<<dim3(4, Tt), 256>>>(hsd, Wfc);
    fc_reduce<<<(Bz * OUTL + 255) / 256, 256>>>(bfc, decoded);
}

// round 15
// speedup vs baseline: 1.6314x; 1.6314x over previous
#include <cuda_runtime.h>
#include <math.h>

#define Bz   128
#define Hh   512
#define G4   2048
#define Tt   256
#define INZ  64
#define OUTL 512
#define NBLK 128

typedef unsigned long long u64;

// ---------------- device scratch ----------------
__device__ float g_xpe[(size_t)Tt * Bz * G4];   // [t][b][4H]
__device__ float g_xpd[(size_t)Tt * Bz * G4];
__device__ float g_hse[(size_t)Tt * Hh * Bz];   // [t][h][b] (ring + output)
__device__ float g_hsd[(size_t)Tt * Hh * Bz];
__device__ float g_hA[Hh * Bz];                 // initial h (encoder)
__device__ float g_h2A[Hh * Bz];                // initial h (decoder)
__device__ float g_fcp[(size_t)Tt * Bz * OUTL];
__device__ unsigned g_ck[8];                    // [layer][chunk] producer counters

// ---------------- f32x2 helpers ----------------
__device__ __forceinline__ u64 pack2(float lo, float hi) {
    u64 r; asm("mov.b64 %0,{%1,%2};" : "=l"(r) : "f"(lo), "f"(hi)); return r;
}
__device__ __forceinline__ void unpack2(u64 v, float& lo, float& hi) {
    asm("mov.b64 {%0,%1},%2;" : "=f"(lo), "=f"(hi) : "l"(v));
}
__device__ __forceinline__ u64 fma2(u64 a, u64 b, u64 c) {
    u64 d; asm("fma.rn.f32x2 %0,%1,%2,%3;" : "=l"(d) : "l"(a), "l"(b), "l"(c)); return d;
}
__device__ __forceinline__ u64 add2(u64 a, u64 b) {
    u64 d; asm("add.rn.f32x2 %0,%1,%2;" : "=l"(d) : "l"(a), "l"(b)); return d;
}
__device__ __forceinline__ float fsig(float x) { return __fdividef(1.f, 1.f + __expf(-x)); }
__device__ __forceinline__ float ftanh_(float x) { return 2.f * fsig(2.f * x) - 1.f; }
__device__ __forceinline__ unsigned ld_acq(const unsigned* p) {
    unsigned v; asm volatile("ld.acquire.gpu.u32 %0,[%1];" : "=r"(v) : "l"(p) : "memory"); return v;
}
__device__ __forceinline__ void red_rel_add(unsigned* p, unsigned v) {
    asm volatile("red.release.gpu.global.add.u32 [%0],%1;" :: "l"(p), "r"(v) : "memory");
}

// ---------------- init ----------------
__global__ void init_h(const float* __restrict__ h0e, const float* __restrict__ h0d) {
    int i = blockIdx.x * blockDim.x + threadIdx.x;
    if (i < Hh * Bz) {
        int k = i >> 7, b = i & 127;
        g_hA[i]  = h0e[b * Hh + k];
        g_h2A[i] = h0d[b * Hh + k];
    }
}
__global__ void init_bar() {
    if (threadIdx.x < 8) g_ck[threadIdx.x] = 0u;
}

// ---------------- input projection GEMM (f32x2) ----------------
template <int MODE>
__global__ void __launch_bounds__(256)
inproj_gemm(const float* __restrict__ A_or_x, const float* __restrict__ W,
            const float* __restrict__ b0v, const float* __restrict__ b1v,
            float* __restrict__ out, int K) {
    __shared__ __align__(16) float As[8][128];
    __shared__ __align__(16) float Bs[8][128];

    const int m0  = blockIdx.y * 128;
    const int n0  = blockIdx.x * 128;
    const int tid = threadIdx.x;
    const int txx = tid & 15;
    const int tyy = tid >> 4;
    const int lrow = tid >> 1;
    const int lkq  = (tid & 1) * 4;
    const int arow = tid >> 5;
    const int acol = (tid & 31) * 4;

    u64 acc[8][4];
#pragma unroll
    for (int i = 0; i < 8; i++)
#pragma unroll
        for (int j = 0; j < 4; j++) acc[i][j] = 0ull;

    float4 aPf, bPf;
    float  aPfS[4];

    if (MODE == 1) {
        aPf = *reinterpret_cast<const float4*>(
            &A_or_x[(size_t)blockIdx.y * Hh * Bz + (size_t)arow * Bz + acol]);
    } else {
        int m = m0 + lrow;
        int tt = m >> 7, b = m & 127;
#pragma unroll
        for (int i = 0; i < 4; i++)
            aPfS[i] = A_or_x[(size_t)b * (INZ * Tt) + (size_t)(lkq + i) * Tt + tt];
    }
    bPf = *reinterpret_cast<const float4*>(&W[(size_t)(n0 + lrow) * K + lkq]);

    for (int k0 = 0; k0 < K; k0 += 8) {
        if (MODE == 1) {
            *reinterpret_cast<float4*>(&As[arow][acol]) = aPf;
        } else {
#pragma unroll
            for (int i = 0; i < 4; i++) As[lkq + i][lrow] = aPfS[i];
        }
        Bs[lkq + 0][lrow] = bPf.x; Bs[lkq + 1][lrow] = bPf.y;
        Bs[lkq + 2][lrow] = bPf.z; Bs[lkq + 3][lrow] = bPf.w;
        __syncthreads();

        int kn = k0 + 8;
        if (kn < K) {
            if (MODE == 1) {
                aPf = *reinterpret_cast<const float4*>(
                    &A_or_x[(size_t)blockIdx.y * Hh * Bz + (size_t)(kn + arow) * Bz + acol]);
            } else {
                int m = m0 + lrow;
                int tt = m >> 7, b = m & 127;
#pragma unroll
                for (int i = 0; i < 4; i++)
                    aPfS[i] = A_or_x[(size_t)b * (INZ * Tt) + (size_t)(kn + lkq + i) * Tt + tt];
            }
            bPf = *reinterpret_cast<const float4*>(&W[(size_t)(n0 + lrow) * K + kn + lkq]);
        }

#pragma unroll
        for (int kk = 0; kk < 8; kk++) {
            float a[8];
            *reinterpret_cast<float4*>(&a[0]) = *reinterpret_cast<const float4*>(&As[kk][tyy * 8]);
            *reinterpret_cast<float4*>(&a[4]) = *reinterpret_cast<const float4*>(&As[kk][tyy * 8 + 4]);
            ulonglong2 bp01 = *reinterpret_cast<const ulonglong2*>(&Bs[kk][txx * 8]);
            ulonglong2 bp23 = *reinterpret_cast<const ulonglong2*>(&Bs[kk][txx * 8 + 4]);
            u64 bp[4] = {bp01.x, bp01.y, bp23.x, bp23.y};
#pragma unroll
            for (int i = 0; i < 8; i++) {
                u64 as = pack2(a[i], a[i]);
#pragma unroll
                for (int j = 0; j < 4; j++)
                    acc[i][j] = fma2(as, bp[j], acc[i][j]);
            }
        }
        __syncthreads();
    }

#pragma unroll
    for (int i = 0; i < 8; i++) {
        int m = m0 + tyy * 8 + i;
#pragma unroll
        for (int j = 0; j < 4; j++) {
            int n = n0 + txx * 8 + 2 * j;
            float lo, hi; unpack2(acc[i][j], lo, hi);
            float2 v = make_float2(lo + b0v[n] + b1v[n], hi + b0v[n + 1] + b1v[n + 1]);
            *reinterpret_cast<float2*>(&out[(size_t)m * G4 + n]) = v;
        }
    }
}

// ---------------- persistent LSTM: dense-h tile, 8-way k-split ----------------
// 128 blocks x 512 threads (16 warps = 8 k-slices x 2 b-halves). Block owns
// 4 hidx x 4 gates (smem ws[k][hh*4+q]). Warp (ks, bh): 16 k-rows per chunk,
// 64 b. Lane (rh, bo): 4 CONTIGUOUS b x 8 gate-rows -> h load is one dense
// LDS.128/kk, w 2 broadcast LDS.128. acc[4][4]. Reduction: 64KB dump into
// freed hb, each of 512 threads sums 8 partials for one (b,hh) cell. tid0
// counter polls + block syncs; h ring in hs_t (single store); c in registers.
__global__ void __launch_bounds__(512, 1)
lstm_persistent(const float* __restrict__ xp_all,   // [t][b][2048]
                const float* __restrict__ whh,      // [2048][512]
                const float* __restrict__ c0,       // [b][512]
                const float* __restrict__ h0buf,    // [512][128] initial h
                float* __restrict__ hs_t,           // [t][512][128] ring + output
                int layer) {
    extern __shared__ char sm_[];
    float* ws    = (float*)sm_;                    // [512][16]  32KB
    float* hb    = (float*)(sm_ + 32768);          // [2][128][128] 128KB (reused as red)
    u64*   red64 = (u64*)(sm_ + 32768);            // [8][64][17] u64 overlay
    float* xs    = (float*)(sm_ + 32768 + 135168); // [128][20] 10KB

    const int tid  = threadIdx.x;
    const int lane = tid & 31;
    const int wrp  = tid >> 5;
    const int ks   = wrp & 7;
    const int bh   = wrp >> 3;
    const int rh   = lane >> 4;
    const int bo   = lane & 15;
    const int hidx0 = blockIdx.x * 4;
    const int myGrp = blockIdx.x >> 5;

    const int eb  = tid & 127;
    const int ehh = tid >> 7;
    const int erh = ehh >> 1, ehp = ehh & 1;
    const int e_bh = eb >> 6;
    const int e_bo = (eb >> 2) & 15;
    const int e_j  = eb & 3;
    const int rd_off = (e_bh * 32 + erh * 16 + e_bo) * 17 + e_j * 4 + ehp * 2;

    unsigned* ck = &g_ck[layer * 4];

    for (int r = tid; r < 8192; r += 512) {
        int k = r & 511, idx = r >> 9;
        int hh = idx >> 2, q = idx & 3;
        ws[k * 16 + idx] = whh[(size_t)(q * Hh + hidx0 + hh) * Hh + k];
    }
    float creg = c0[(size_t)eb * Hh + hidx0 + ehh];

    const unsigned hb_s = (unsigned)__cvta_generic_to_shared(hb);

    float4 xr = *reinterpret_cast<const float4*>(
        &xp_all[(size_t)(tid >> 2) * G4 + (tid & 3) * Hh + hidx0]);

    __syncthreads();

    for (int t = 0; t < Tt; t++) {
        const float* hp = (t == 0) ? h0buf : (hs_t + (size_t)(t - 1) * Hh * Bz);

        if (tid == 0 && t > 0) {
            unsigned target = (unsigned)(32 * t);
            while (ld_acq(&ck[0]) < target) {}
        }
        __syncthreads();
        {
            unsigned sa = hb_s + tid * 16;
            const char* gp = (const char*)hp + tid * 16;
#pragma unroll
            for (int i = 0; i < 8; i++)
                asm volatile("cp.async.cg.shared.global [%0], [%1], 16;"
                             :: "r"(sa + i * 8192), "l"(gp + i * 8192));
            asm volatile("cp.async.commit_group;" ::: "memory");
        }

        u64 acc[4][4];
#pragma unroll
        for (int j = 0; j < 4; j++)
#pragma unroll
            for (int p = 0; p < 4; p++) acc[j][p] = 0ull;

#pragma unroll
        for (int c = 0; c < 4; c++) {
            asm volatile("cp.async.wait_group 0;" ::: "memory");
            if (tid == 0 && c < 3 && t > 0) {
                unsigned target = (unsigned)(32 * t);
                while (ld_acq(&ck[c + 1]) < target) {}
            }
            __syncthreads();

            if (c < 3) {
                unsigned sa = hb_s + ((c + 1) & 1) * 65536 + tid * 16;
                const char* gp = (const char*)(hp + (c + 1) * 16384) + tid * 16;
#pragma unroll
                for (int i = 0; i < 8; i++)
                    asm volatile("cp.async.cg.shared.global [%0], [%1], 16;"
                                 :: "r"(sa + i * 8192), "l"(gp + i * 8192));
                asm volatile("cp.async.commit_group;" ::: "memory");
            }

            const float* bufk = hb + (c & 1) * 16384 + (size_t)(ks * 16) * 128 + bh * 64 + bo * 4;
            const float* wsk  = ws + (size_t)(c * 128 + ks * 16) * 16 + rh * 8;
#pragma unroll
            for (int kk = 0; kk < 16; kk++) {
                float4 hv = *reinterpret_cast<const float4*>(bufk + (size_t)kk * 128);
                ulonglong2 wa = *reinterpret_cast<const ulonglong2*>(wsk + (size_t)kk * 16);
                ulonglong2 wb = *reinterpret_cast<const ulonglong2*>(wsk + (size_t)kk * 16 + 4);
                float hvv[4] = {hv.x, hv.y, hv.z, hv.w};
#pragma unroll
                for (int j = 0; j < 4; j++) {
                    u64 hs = pack2(hvv[j], hvv[j]);
                    acc[j][0] = fma2(hs, wa.x, acc[j][0]);
                    acc[j][1] = fma2(hs, wa.y, acc[j][1]);
                    acc[j][2] = fma2(hs, wb.x, acc[j][2]);
                    acc[j][3] = fma2(hs, wb.y, acc[j][3]);
                }
            }
        }

        __syncthreads();

        *reinterpret_cast<float4*>(&xs[(tid >> 2) * 20 + (tid & 3) * 4]) = xr;

        {
            u64* rp = red64 + (size_t)ks * 1088 + (size_t)(bh * 32 + lane) * 17;
#pragma unroll
            for (int j = 0; j < 4; j++)
#pragma unroll
                for (int p = 0; p < 4; p++) rp[j * 4 + p] = acc[j][p];
        }
        __syncthreads();

        u64 s0 = 0ull, s1 = 0ull;
        {
            const u64* rp = red64 + rd_off;
#pragma unroll
            for (int g = 0; g < 8; g++) {
                s0 = add2(s0, rp[(size_t)g * 1088]);
                s1 = add2(s1, rp[(size_t)g * 1088 + 1]);
            }
        }

        {
            float gi_, gf_, gg_, go_;
            unpack2(s0, gi_, gf_);
            unpack2(s1, gg_, go_);
            const float* xb = xs + eb * 20 + ehh;
            float gi = gi_ + xb[0];
            float gf = gf_ + xb[4];
            float gg = gg_ + xb[8];
            float go = go_ + xb[12];
            float cc = fsig(gf) * creg + fsig(gi) * ftanh_(gg);
            creg = cc;
            float h = fsig(go) * ftanh_(cc);
            hs_t[(size_t)t * Hh * Bz + (hidx0 + ehh) * Bz + eb] = h;
        }

        if (t + 1 < Tt)
            xr = *reinterpret_cast<const float4*>(
                &xp_all[(size_t)(t + 1) * Bz * G4 +
                        (size_t)(tid >> 2) * G4 + (tid & 3) * Hh + hidx0]);

        __syncthreads();
        if (tid == 0) red_rel_add(&ck[myGrp], 1u);
    }
}

// ---------------- encoder output transpose ----------------
__global__ void __launch_bounds__(256)
enc_transpose(const float* __restrict__ hs_t, float* __restrict__ out) {
    __shared__ float tile[32][33];
    int t0 = blockIdx.x * 32, b0 = blockIdx.y * 32, h = blockIdx.z;
    int tx = threadIdx.x & 31, ty = threadIdx.x >> 5;
#pragma unroll
    for (int i = ty; i < 32; i += 8)
        tile[i][tx] = hs_t[(size_t)(t0 + i) * (Hh * Bz) + (size_t)h * Bz + b0 + tx];
    __syncthreads();
#pragma unroll
    for (int i = ty; i < 32; i += 8)
        out[(size_t)(b0 + i) * (Hh * Tt) + (size_t)h * Tt + t0 + tx] = tile[tx][i];
}

// ---------------- FC partial GEMM (f32x2, k-split over t) ----------------
__global__ void __launch_bounds__(256)
fc_partial(const float* __restrict__ hsd_t, const float* __restrict__ Wfc) {
    const int t  = blockIdx.y;
    const int o0 = blockIdx.x * 128;
    const int tid = threadIdx.x;
    const int txx = tid & 15;
    const int tyy = tid >> 4;
    const int lrow = tid >> 1;
    const int lkq  = (tid & 1) * 4;
    const int arow = tid >> 5;
    const int acol = (tid & 31) * 4;

    __shared__ __align__(16) float As[8][128];
    __shared__ __align__(16) float Bs[8][128];

    u64 acc[8][4];
#pragma unroll
    for (int i = 0; i < 8; i++)
#pragma unroll
        for (int j = 0; j < 4; j++) acc[i][j] = 0ull;

    const float* Abase = hsd_t + (size_t)t * (Hh * Bz);

    for (int h0 = 0; h0 < Hh; h0 += 8) {
        *reinterpret_cast<float4*>(&As[arow][acol]) =
            *reinterpret_cast<const float4*>(&Abase[(size_t)(h0 + arow) * Bz + acol]);
#pragma unroll
        for (int i = 0; i < 4; i++)
            Bs[lkq + i][lrow] = Wfc[(size_t)(o0 + lrow) * (Hh * Tt) + (size_t)(h0 + lkq + i) * Tt + t];
        __syncthreads();
#pragma unroll
        for (int kk = 0; kk < 8; kk++) {
            float a[8];
            *reinterpret_cast<float4*>(&a[0]) = *reinterpret_cast<const float4*>(&As[kk][tyy * 8]);
            *reinterpret_cast<float4*>(&a[4]) = *reinterpret_cast<const float4*>(&As[kk][tyy * 8 + 4]);
            ulonglong2 bp01 = *reinterpret_cast<const ulonglong2*>(&Bs[kk][txx * 8]);
            ulonglong2 bp23 = *reinterpret_cast<const ulonglong2*>(&Bs[kk][txx * 8 + 4]);
            u64 bp[4] = {bp01.x, bp01.y, bp23.x, bp23.y};
#pragma unroll
            for (int i = 0; i < 8; i++) {
                u64 as = pack2(a[i], a[i]);
#pragma unroll
                for (int j = 0; j < 4; j++)
                    acc[i][j] = fma2(as, bp[j], acc[i][j]);
            }
        }
        __syncthreads();
    }

    float* part = g_fcp + (size_t)t * (Bz * OUTL);
#pragma unroll
    for (int i = 0; i < 8; i++) {
        int b = tyy * 8 + i;
#pragma unroll
        for (int j = 0; j < 4; j++) {
            float lo, hi; unpack2(acc[i][j], lo, hi);
            *reinterpret_cast<float2*>(&part[(size_t)b * OUTL + o0 + txx * 8 + 2 * j]) =
                make_float2(lo, hi);
        }
    }
}

__global__ void fc_reduce(const float* __restrict__ bfc, float* __restrict__ decoded) {
    int i = blockIdx.x * blockDim.x + threadIdx.x;
    if (i >= Bz * OUTL) return;
    float s = bfc[i & (OUTL - 1)];
    for (int t = 0; t < Tt; t++) s += g_fcp[(size_t)t * (Bz * OUTL) + i];
    decoded[i] = s;
}

// ---------------- launch ----------------
extern "C" void kernel_launch(void* const* d_in, const int* in_sizes, int n_in,
                              void* d_out, int out_size) {
    const float* x     = (const float*)d_in[0];
    const float* h0e   = (const float*)d_in[1];
    const float* c0e   = (const float*)d_in[2];
    const float* Wih_e = (const float*)d_in[3];
    const float* Whh_e = (const float*)d_in[4];
    const float* bih_e = (const float*)d_in[5];
    const float* bhh_e = (const float*)d_in[6];
    const float* h0d   = (const float*)d_in[7];
    const float* c0d   = (const float*)d_in[8];
    const float* Wih_d = (const float*)d_in[9];
    const float* Whh_d = (const float*)d_in[10];
    const float* bih_d = (const float*)d_in[11];
    const float* bhh_d = (const float*)d_in[12];
    const float* Wfc   = (const float*)d_in[13];
    const float* bfc   = (const float*)d_in[14];

    float* out = (float*)d_out;
    float* enc_out = out;
    float* decoded = out + (size_t)Bz * Hh * Tt;

    float *xpe, *xpd, *hse, *hsd, *hA, *h2A;
    cudaGetSymbolAddress((void**)&xpe, g_xpe);
    cudaGetSymbolAddress((void**)&xpd, g_xpd);
    cudaGetSymbolAddress((void**)&hse, g_hse);
    cudaGetSymbolAddress((void**)&hsd, g_hsd);
    cudaGetSymbolAddress((void**)&hA,  g_hA);
    cudaGetSymbolAddress((void**)&h2A, g_h2A);

    const int SMEM = 32768 + 135168 + 10240;   // 178176
    cudaFuncSetAttribute(lstm_persistent, cudaFuncAttributeMaxDynamicSharedMemorySize, SMEM);

    init_h<<<(Hh * Bz + 255) / 256, 256>>>(h0e, h0d);
    init_bar<<<1, 32>>>();

    inproj_gemm<0><<<dim3(16, 256), 256>>>(x, Wih_e, bih_e, bhh_e, xpe, INZ);

    lstm_persistent<<<NBLK, 512, SMEM>>>(xpe, Whh_e, c0e, hA, hse, 0);

    inproj_gemm<1><<<dim3(16, 256), 256>>>(hse, Wih_d, bih_d, bhh_d, xpd, Hh);

    lstm_persistent<<<NBLK, 512, SMEM>>>(xpd, Whh_d, c0d, h2A, hsd, 1);

    enc_transpose<<<dim3(Tt / 32, Bz / 32, Hh), 256>>>(hse, enc_out);

    fc_partial<<<dim3(4, Tt), 256>>>(hsd, Wfc);
    fc_reduce<<<(Bz * OUTL + 255) / 256, 256>>>(bfc, decoded);
}